// round 16
// baseline (speedup 1.0000x reference)
#include <cuda_runtime.h>
#include <cuda_bf16.h>
#include <math.h>

// Problem constants
#define Bn   8
#define Ntok 1024
#define Dd   768
#define Hh   8
#define Ss   3072
#define HDd  384
#define Mtok 8192   // Bn*Ntok

// ---------------- scratch (device globals; no allocation allowed) ----------------
__device__ __align__(16) float g_xn[(size_t)Mtok * Dd];
__device__ __align__(16) float g_q [(size_t)Mtok * Ss];
__device__ __align__(16) float g_k [(size_t)Mtok * Ss];
__device__ __align__(16) float g_v [(size_t)Mtok * Ss];
__device__ __align__(16) float g_y [(size_t)Mtok * Ss];
__device__ __align__(16) float g_mem[(size_t)Hh * HDd * HDd];
__device__ float g_xpart[8 * Bn * Dd];    // [chunk][b][d] partial token sums of xn
__device__ float g_kpart[4 * Bn * Ss];    // [chunk][b][s] partial token sums of k-hat
__device__ float g_residue[Mtok];
__device__ float g_read[Bn * Hh];
__device__ float g_wbar[Hh];

// A-smem row strides (floats)
#define ASTR 132
#define ASTR3 68

// ---------------- packed f32x2 helpers (Blackwell double-rate FP32) ----------------
#define PACK2(dst, lo, hi) \
    asm("mov.b64 %0, {%1, %2};" : "=l"(dst) : "f"(lo), "f"(hi))
#define UNPACK2(lo, hi, src) \
    asm("mov.b64 {%0, %1}, %2;" : "=f"(lo), "=f"(hi) : "l"(src))
#define FMA2(acc, a, b) \
    asm("fma.rn.f32x2 %0, %1, %2, %0;" : "+l"(acc) : "l"(a), "l"(b))

// ---------------- 1. LayerNorm + residue gate (warp-per-token, no barriers) ----------------
__global__ void ln_kernel(const float* __restrict__ x, const float* __restrict__ ln_g,
                          const float* __restrict__ ln_b, const float* __restrict__ w_res,
                          const float* __restrict__ b_res) {
    int warp = threadIdx.x >> 5, lane = threadIdx.x & 31;
    int m = blockIdx.x * 8 + warp;
    const float* xr = x + (size_t)m * Dd;
    float v[24]; float s = 0.f, sq = 0.f;
    #pragma unroll
    for (int i = 0; i < 24; i++) {
        float t = xr[lane + 32 * i];
        v[i] = t; s += t; sq += t * t;
    }
    #pragma unroll
    for (int o = 16; o; o >>= 1) {
        s  += __shfl_xor_sync(0xffffffffu, s,  o);
        sq += __shfl_xor_sync(0xffffffffu, sq, o);
    }
    float mu   = s * (1.f / Dd);
    float var  = sq * (1.f / Dd) - mu * mu;
    float rstd = rsqrtf(var + 1e-5f);
    float dot = 0.f;
    #pragma unroll
    for (int i = 0; i < 24; i++) {
        int d = lane + 32 * i;
        float xn = (v[i] - mu) * rstd * ln_g[d] + ln_b[d];
        g_xn[(size_t)m * Dd + d] = xn;
        dot += xn * w_res[d];
    }
    #pragma unroll
    for (int o = 16; o; o >>= 1) dot += __shfl_xor_sync(0xffffffffu, dot, o);
    if (lane == 0) g_residue[m] = 1.f / (1.f + expf(-(dot + b_res[0])));
}

// ---------------- 2a. token-sum partials of xn ----------------
__global__ void xpart_kernel() {
    int b = blockIdx.x >> 3, c = blockIdx.x & 7;
    int d = blockIdx.y * 256 + threadIdx.x;
    const float* base = g_xn + ((size_t)(b * Ntok + c * 128)) * Dd + d;
    float s = 0.f;
    for (int n = 0; n < 128; n++) s += base[(size_t)n * Dd];
    g_xpart[((size_t)c * Bn + b) * Dd + d] = s;
}

// ---------------- 2b. read/write gates + write-mean ----------------
__global__ void gates_kernel(const float* __restrict__ w_rg, const float* __restrict__ b_rg,
                             const float* __restrict__ w_wg, const float* __restrict__ b_wg) {
    __shared__ float s_gate[2][64];   // [gate][b*H+h]
    int tid = threadIdx.x, warp = tid >> 5, lane = tid & 31;
    for (int job = warp; job < 128; job += 8) {
        int gate = job & 1, bh = job >> 1, b = bh >> 3, h = bh & 7;
        const float* W = gate ? w_wg : w_rg;
        float sacc = 0.f;
        for (int d = lane; d < Dd; d += 32) {
            float xm = 0.f;
            #pragma unroll
            for (int c = 0; c < 8; c++) xm += g_xpart[((size_t)c * Bn + b) * Dd + d];
            sacc += xm * W[(size_t)d * Hh + h];
        }
        #pragma unroll
        for (int o = 16; o; o >>= 1) sacc += __shfl_xor_sync(0xffffffffu, sacc, o);
        if (lane == 0) {
            float bias = gate ? b_wg[h] : b_rg[h];
            s_gate[gate][bh] = 1.f / (1.f + expf(-(sacc * (1.f / Ntok) + bias)));
        }
    }
    __syncthreads();
    if (tid < 64) g_read[tid] = s_gate[0][tid];
    if (tid < 8) {
        float s = 0.f;
        #pragma unroll
        for (int b = 0; b < 8; b++) s += s_gate[1][b * Hh + tid];
        g_wbar[tid] = s * (1.f / Bn);
    }
}

// ---------------- 3. GEMM1: qkv = xn @ w_in + b_in, fused activation split ----------------
__global__ void gemm1_kernel(const float* __restrict__ w_in, const float* __restrict__ b_in) {
    const int K = Dd, NN = 3 * Ss;
    __shared__ float As[2][8 * ASTR];
    __shared__ float Bs[2][8 * 128];
    int tid = threadIdx.x;
    int bRow = blockIdx.y * 128, bCol = blockIdx.x * 128;
    int aR0 = tid >> 1, aC0 = (tid & 1) * 4;
    int bR0 = tid >> 5, bC0 = (tid & 31) * 4;
    const float* Aptr = g_xn + (size_t)bRow * K;
    const float* Bptr = w_in + bCol;
    unsigned long long acc2[8][4] = {};
    int ra = (tid >> 4) * 4, cb = (tid & 15) * 4;

    float4 pa = *(const float4*)(Aptr + (size_t)aR0 * K + aC0);
    float4 pb = *(const float4*)(Bptr + (size_t)bR0 * NN + bC0);
    As[0][(aC0 + 0) * ASTR + aR0] = pa.x;  As[0][(aC0 + 1) * ASTR + aR0] = pa.y;
    As[0][(aC0 + 2) * ASTR + aR0] = pa.z;  As[0][(aC0 + 3) * ASTR + aR0] = pa.w;
    *(float4*)&Bs[0][bR0 * 128 + bC0] = pb;
    __syncthreads();

    const int KT = K / 8;
    for (int kt = 0; kt < KT; kt++) {
        int s = kt & 1;
        bool pre = (kt + 1 < KT);
        if (pre) {
            int kc = (kt + 1) * 8;
            pa = *(const float4*)(Aptr + (size_t)aR0 * K + kc + aC0);
            pb = *(const float4*)(Bptr + (size_t)(kc + bR0) * NN + bC0);
        }
        #pragma unroll
        for (int kk = 0; kk < 8; kk++) {
            float rM[8];
            *(float4*)&rM[0] = *(const float4*)&As[s][kk * ASTR + ra];
            *(float4*)&rM[4] = *(const float4*)&As[s][kk * ASTR + ra + 64];
            __align__(16) unsigned long long b2[4];
            *(float4*)&b2[0] = *(const float4*)&Bs[s][kk * 128 + cb];
            *(float4*)&b2[2] = *(const float4*)&Bs[s][kk * 128 + cb + 64];
            #pragma unroll
            for (int i = 0; i < 8; i++) {
                unsigned long long a2;
                PACK2(a2, rM[i], rM[i]);
                FMA2(acc2[i][0], a2, b2[0]);
                FMA2(acc2[i][1], a2, b2[1]);
                FMA2(acc2[i][2], a2, b2[2]);
                FMA2(acc2[i][3], a2, b2[3]);
            }
        }
        if (pre) {
            int d = s ^ 1;
            As[d][(aC0 + 0) * ASTR + aR0] = pa.x;  As[d][(aC0 + 1) * ASTR + aR0] = pa.y;
            As[d][(aC0 + 2) * ASTR + aR0] = pa.z;  As[d][(aC0 + 3) * ASTR + aR0] = pa.w;
            *(float4*)&Bs[d][bR0 * 128 + bC0] = pb;
            __syncthreads();
        }
    }

    float acc[8][8];
    #pragma unroll
    for (int i = 0; i < 8; i++) {
        UNPACK2(acc[i][0], acc[i][1], acc2[i][0]);
        UNPACK2(acc[i][2], acc[i][3], acc2[i][1]);
        UNPACK2(acc[i][4], acc[i][5], acc2[i][2]);
        UNPACK2(acc[i][6], acc[i][7], acc2[i][3]);
    }

    int region = bCol / Ss;                 // uniform per block: 0=q, 1=k, 2=v
    float* dst = (region == 0) ? g_q : (region == 1 ? g_k : g_v);
    int colBase = bCol - region * Ss;
    #pragma unroll
    for (int i = 0; i < 8; i++) {
        int row = bRow + ra + (i < 4 ? i : 64 + i - 4);
        #pragma unroll
        for (int half = 0; half < 2; half++) {
            int cB = cb + half * 64;
            float4 v;
            v.x = acc[i][half * 4 + 0] + b_in[bCol + cB + 0];
            v.y = acc[i][half * 4 + 1] + b_in[bCol + cB + 1];
            v.z = acc[i][half * 4 + 2] + b_in[bCol + cB + 2];
            v.w = acc[i][half * 4 + 3] + b_in[bCol + cB + 3];
            if (region < 2) {
                float t;
                t = fmaxf(v.x, 0.f) + 1e-6f; v.x = t * sqrtf(t);
                t = fmaxf(v.y, 0.f) + 1e-6f; v.y = t * sqrtf(t);
                t = fmaxf(v.z, 0.f) + 1e-6f; v.z = t * sqrtf(t);
                t = fmaxf(v.w, 0.f) + 1e-6f; v.w = t * sqrtf(t);
            }
            *(float4*)(dst + (size_t)row * Ss + colBase + cB) = v;
        }
    }
}

// ---------------- 4. token-sum partials of k-hat ----------------
__global__ void kpart_kernel() {
    int b = blockIdx.x;
    int s = blockIdx.y * 256 + threadIdx.x;
    int c = blockIdx.z;
    const float* base = g_k + ((size_t)(b * Ntok + c * 256)) * Ss + s;
    float s0 = 0.f, s1 = 0.f, s2 = 0.f, s3 = 0.f;
    for (int n = 0; n < 256; n += 4) {
        s0 += base[(size_t)(n + 0) * Ss];
        s1 += base[(size_t)(n + 1) * Ss];
        s2 += base[(size_t)(n + 2) * Ss];
        s3 += base[(size_t)(n + 3) * Ss];
    }
    g_kpart[((size_t)c * Bn + b) * Ss + s] = (s0 + s1) + (s2 + s3);
}

// ---------------- 5. per-head state (k^T v, normalized) + EMA; double-buffered ----------------
__global__ void state_kernel(const float* __restrict__ memory) {
    int h = blockIdx.z, d0 = blockIdx.y * 64, e0 = blockIdx.x * 64;
    __shared__ float ks[2][32][64];
    __shared__ float vs[2][32][64];
    int tid = threadIdx.x;
    int tr = (tid >> 4) * 4, tc = (tid & 15) * 4;
    int n1 = tid >> 4, c1 = (tid & 15) * 4;
    float accT[4][4] = {};
    for (int b = 0; b < Bn; b++) {
        unsigned long long accB2[4][2] = {};
        const float* kbase = g_k + (size_t)b * Ntok * Ss + h * HDd + d0;
        const float* vbase = g_v + (size_t)b * Ntok * Ss + h * HDd + e0;
        float4 pk0 = *(const float4*)(kbase + (size_t)n1 * Ss + c1);
        float4 pk1 = *(const float4*)(kbase + (size_t)(n1 + 16) * Ss + c1);
        float4 pv0 = *(const float4*)(vbase + (size_t)n1 * Ss + c1);
        float4 pv1 = *(const float4*)(vbase + (size_t)(n1 + 16) * Ss + c1);
        *(float4*)&ks[0][n1][c1]      = pk0;
        *(float4*)&ks[0][n1 + 16][c1] = pk1;
        *(float4*)&vs[0][n1][c1]      = pv0;
        *(float4*)&vs[0][n1 + 16][c1] = pv1;
        __syncthreads();
        for (int c = 0; c < 32; c++) {
            int s = c & 1;
            bool pre = (c + 1 < 32);
            if (pre) {
                int n0 = (c + 1) * 32;
                pk0 = *(const float4*)(kbase + (size_t)(n0 + n1) * Ss + c1);
                pk1 = *(const float4*)(kbase + (size_t)(n0 + n1 + 16) * Ss + c1);
                pv0 = *(const float4*)(vbase + (size_t)(n0 + n1) * Ss + c1);
                pv1 = *(const float4*)(vbase + (size_t)(n0 + n1 + 16) * Ss + c1);
            }
            #pragma unroll
            for (int n = 0; n < 32; n++) {
                float rk[4];
                *(float4*)&rk[0] = *(const float4*)&ks[s][n][tr];
                __align__(16) unsigned long long b2[2];
                *(float4*)&b2[0] = *(const float4*)&vs[s][n][tc];
                #pragma unroll
                for (int i = 0; i < 4; i++) {
                    unsigned long long a2;
                    PACK2(a2, rk[i], rk[i]);
                    FMA2(accB2[i][0], a2, b2[0]);
                    FMA2(accB2[i][1], a2, b2[1]);
                }
            }
            if (pre) {
                int d = s ^ 1;
                *(float4*)&ks[d][n1][c1]      = pk0;
                *(float4*)&ks[d][n1 + 16][c1] = pk1;
                *(float4*)&vs[d][n1][c1]      = pv0;
                *(float4*)&vs[d][n1 + 16][c1] = pv1;
                __syncthreads();
            }
        }
        #pragma unroll
        for (int i = 0; i < 4; i++) {
            float accB[4];
            UNPACK2(accB[0], accB[1], accB2[i][0]);
            UNPACK2(accB[2], accB[3], accB2[i][1]);
            float kd = 0.f;
            #pragma unroll
            for (int c = 0; c < 4; c++)
                kd += g_kpart[((size_t)c * Bn + b) * Ss + h * HDd + d0 + tr + i];
            float rs = (1.f / Bn) / (kd + 1e-6f);
            #pragma unroll
            for (int j = 0; j < 4; j++) accT[i][j] += accB[j] * rs;
        }
    }
    float wb = g_wbar[h];
    #pragma unroll
    for (int i = 0; i < 4; i++)
        #pragma unroll
        for (int j = 0; j < 4; j++) {
            size_t idx = ((size_t)h * HDd + (d0 + tr + i)) * HDd + (e0 + tc + j);
            g_mem[idx] = 0.95f * memory[idx] + 0.05f * wb * accT[i][j];
        }
}

// ---------------- 6. GEMM2: y = read[b,h] * (q_h @ mem_new_h) ----------------
__global__ void gemm2_kernel() {
    const int K = HDd, NN = HDd;
    __shared__ float As[2][8 * ASTR];
    __shared__ float Bs[2][8 * 128];
    int tid = threadIdx.x;
    int h = blockIdx.z;
    int bRow = blockIdx.y * 128, bCol = blockIdx.x * 128;
    int aR0 = tid >> 1, aC0 = (tid & 1) * 4;
    int bR0 = tid >> 5, bC0 = (tid & 31) * 4;
    const float* Aptr = g_q + (size_t)bRow * Ss + h * HDd;
    const float* Bptr = g_mem + (size_t)h * HDd * HDd + bCol;
    unsigned long long acc2[8][4] = {};
    int ra = (tid >> 4) * 4, cb = (tid & 15) * 4;

    float4 pa = *(const float4*)(Aptr + (size_t)aR0 * Ss + aC0);
    float4 pb = *(const float4*)(Bptr + (size_t)bR0 * NN + bC0);
    As[0][(aC0 + 0) * ASTR + aR0] = pa.x;  As[0][(aC0 + 1) * ASTR + aR0] = pa.y;
    As[0][(aC0 + 2) * ASTR + aR0] = pa.z;  As[0][(aC0 + 3) * ASTR + aR0] = pa.w;
    *(float4*)&Bs[0][bR0 * 128 + bC0] = pb;
    __syncthreads();

    const int KT = K / 8;
    for (int kt = 0; kt < KT; kt++) {
        int s = kt & 1;
        bool pre = (kt + 1 < KT);
        if (pre) {
            int kc = (kt + 1) * 8;
            pa = *(const float4*)(Aptr + (size_t)aR0 * Ss + kc + aC0);
            pb = *(const float4*)(Bptr + (size_t)(kc + bR0) * NN + bC0);
        }
        #pragma unroll
        for (int kk = 0; kk < 8; kk++) {
            float rM[8];
            *(float4*)&rM[0] = *(const float4*)&As[s][kk * ASTR + ra];
            *(float4*)&rM[4] = *(const float4*)&As[s][kk * ASTR + ra + 64];
            __align__(16) unsigned long long b2[4];
            *(float4*)&b2[0] = *(const float4*)&Bs[s][kk * 128 + cb];
            *(float4*)&b2[2] = *(const float4*)&Bs[s][kk * 128 + cb + 64];
            #pragma unroll
            for (int i = 0; i < 8; i++) {
                unsigned long long a2;
                PACK2(a2, rM[i], rM[i]);
                FMA2(acc2[i][0], a2, b2[0]);
                FMA2(acc2[i][1], a2, b2[1]);
                FMA2(acc2[i][2], a2, b2[2]);
                FMA2(acc2[i][3], a2, b2[3]);
            }
        }
        if (pre) {
            int d = s ^ 1;
            As[d][(aC0 + 0) * ASTR + aR0] = pa.x;  As[d][(aC0 + 1) * ASTR + aR0] = pa.y;
            As[d][(aC0 + 2) * ASTR + aR0] = pa.z;  As[d][(aC0 + 3) * ASTR + aR0] = pa.w;
            *(float4*)&Bs[d][bR0 * 128 + bC0] = pb;
            __syncthreads();
        }
    }

    float acc[8][8];
    #pragma unroll
    for (int i = 0; i < 8; i++) {
        UNPACK2(acc[i][0], acc[i][1], acc2[i][0]);
        UNPACK2(acc[i][2], acc[i][3], acc2[i][1]);
        UNPACK2(acc[i][4], acc[i][5], acc2[i][2]);
        UNPACK2(acc[i][6], acc[i][7], acc2[i][3]);
    }

    float scale = g_read[(bRow >> 10) * Hh + h];   // 128-row tile lies within one batch
    #pragma unroll
    for (int i = 0; i < 8; i++) {
        int row = bRow + ra + (i < 4 ? i : 64 + i - 4);
        #pragma unroll
        for (int half = 0; half < 2; half++) {
            int cB = cb + half * 64;
            float4 v;
            v.x = acc[i][half * 4 + 0] * scale;
            v.y = acc[i][half * 4 + 1] * scale;
            v.z = acc[i][half * 4 + 2] * scale;
            v.w = acc[i][half * 4 + 3] * scale;
            *(float4*)(g_y + (size_t)row * Ss + h * HDd + bCol + cB) = v;
        }
    }
}

// ---------------- 7. GEMM3 (64x128 tiles): out = residue*(y@w_out + b_out) + (1-residue)*x ----------------
__global__ void gemm3_kernel(const float* __restrict__ x, const float* __restrict__ w_out,
                             const float* __restrict__ b_out, float* __restrict__ out) {
    const int K = Ss, NN = Dd;
    __shared__ float As[2][8 * ASTR3];
    __shared__ float Bs[2][8 * 128];
    int tid = threadIdx.x;
    int bRow = blockIdx.y * 64, bCol = blockIdx.x * 128;
    int aR0 = tid >> 1, aC0 = (tid & 1) * 4;   // valid when tid < 128
    bool aAct = (tid < 128);
    int bR0 = tid >> 5, bC0 = (tid & 31) * 4;
    const float* Aptr = g_y + (size_t)bRow * K;
    const float* Bptr = w_out + bCol;
    unsigned long long acc2[4][4] = {};
    int ra2 = (tid >> 4) * 2, cb = (tid & 15) * 4;

    float4 pa = make_float4(0.f, 0.f, 0.f, 0.f);
    if (aAct) pa = *(const float4*)(Aptr + (size_t)aR0 * K + aC0);
    float4 pb = *(const float4*)(Bptr + (size_t)bR0 * NN + bC0);
    if (aAct) {
        As[0][(aC0 + 0) * ASTR3 + aR0] = pa.x;  As[0][(aC0 + 1) * ASTR3 + aR0] = pa.y;
        As[0][(aC0 + 2) * ASTR3 + aR0] = pa.z;  As[0][(aC0 + 3) * ASTR3 + aR0] = pa.w;
    }
    *(float4*)&Bs[0][bR0 * 128 + bC0] = pb;
    __syncthreads();

    const int KT = K / 8;
    for (int kt = 0; kt < KT; kt++) {
        int s = kt & 1;
        bool pre = (kt + 1 < KT);
        if (pre) {
            int kc = (kt + 1) * 8;
            if (aAct) pa = *(const float4*)(Aptr + (size_t)aR0 * K + kc + aC0);
            pb = *(const float4*)(Bptr + (size_t)(kc + bR0) * NN + bC0);
        }
        #pragma unroll
        for (int kk = 0; kk < 8; kk++) {
            float rM[4];
            *(float2*)&rM[0] = *(const float2*)&As[s][kk * ASTR3 + ra2];
            *(float2*)&rM[2] = *(const float2*)&As[s][kk * ASTR3 + ra2 + 32];
            __align__(16) unsigned long long b2[4];
            *(float4*)&b2[0] = *(const float4*)&Bs[s][kk * 128 + cb];
            *(float4*)&b2[2] = *(const float4*)&Bs[s][kk * 128 + cb + 64];
            #pragma unroll
            for (int i = 0; i < 4; i++) {
                unsigned long long a2;
                PACK2(a2, rM[i], rM[i]);
                FMA2(acc2[i][0], a2, b2[0]);
                FMA2(acc2[i][1], a2, b2[1]);
                FMA2(acc2[i][2], a2, b2[2]);
                FMA2(acc2[i][3], a2, b2[3]);
            }
        }
        if (pre) {
            int d = s ^ 1;
            if (aAct) {
                As[d][(aC0 + 0) * ASTR3 + aR0] = pa.x;  As[d][(aC0 + 1) * ASTR3 + aR0] = pa.y;
                As[d][(aC0 + 2) * ASTR3 + aR0] = pa.z;  As[d][(aC0 + 3) * ASTR3 + aR0] = pa.w;
            }
            *(float4*)&Bs[d][bR0 * 128 + bC0] = pb;
            __syncthreads();
        }
    }

    float acc[4][8];
    #pragma unroll
    for (int i = 0; i < 4; i++) {
        UNPACK2(acc[i][0], acc[i][1], acc2[i][0]);
        UNPACK2(acc[i][2], acc[i][3], acc2[i][1]);
        UNPACK2(acc[i][4], acc[i][5], acc2[i][2]);
        UNPACK2(acc[i][6], acc[i][7], acc2[i][3]);
    }

    #pragma unroll
    for (int i = 0; i < 4; i++) {
        int row = bRow + (i < 2 ? ra2 + i : 32 + ra2 + (i - 2));
        float r = g_residue[row];
        #pragma unroll
        for (int half = 0; half < 2; half++) {
            int cB = bCol + cb + half * 64;
            const float* xr = x + (size_t)row * Dd + cB;
            float4 xv = *(const float4*)xr;
            float4 v;
            v.x = r * (acc[i][half * 4 + 0] + b_out[cB + 0]) + (1.f - r) * xv.x;
            v.y = r * (acc[i][half * 4 + 1] + b_out[cB + 1]) + (1.f - r) * xv.y;
            v.z = r * (acc[i][half * 4 + 2] + b_out[cB + 2]) + (1.f - r) * xv.z;
            v.w = r * (acc[i][half * 4 + 3] + b_out[cB + 3]) + (1.f - r) * xv.w;
            *(float4*)(out + (size_t)row * Dd + cB) = v;
        }
    }
}

// ---------------- launch ----------------
extern "C" void kernel_launch(void* const* d_in, const int* in_sizes, int n_in,
                              void* d_out, int out_size) {
    (void)in_sizes; (void)n_in; (void)out_size;
    const float* x      = (const float*)d_in[0];
    const float* memory = (const float*)d_in[1];
    const float* ln_g   = (const float*)d_in[2];
    const float* ln_b   = (const float*)d_in[3];
    const float* w_in   = (const float*)d_in[4];
    const float* b_in   = (const float*)d_in[5];
    const float* w_out  = (const float*)d_in[6];
    const float* b_out  = (const float*)d_in[7];
    const float* w_rg   = (const float*)d_in[8];
    const float* b_rg   = (const float*)d_in[9];
    const float* w_wg   = (const float*)d_in[10];
    const float* b_wg   = (const float*)d_in[11];
    const float* w_res  = (const float*)d_in[12];
    const float* b_res  = (const float*)d_in[13];
    float* out = (float*)d_out;

    ln_kernel<<<Mtok / 8, 256>>>(x, ln_g, ln_b, w_res, b_res);
    xpart_kernel<<<dim3(64, 3), 256>>>();
    gates_kernel<<<1, 256>>>(w_rg, b_rg, w_wg, b_wg);
    gemm1_kernel<<<dim3(72, 64), 256>>>(w_in, b_in);
    kpart_kernel<<<dim3(8, 12, 4), 256>>>();
    state_kernel<<<dim3(6, 6, 8), 256>>>(memory);
    gemm2_kernel<<<dim3(3, 64, 8), 256>>>();
    gemm3_kernel<<<dim3(6, 128), 256>>>(x, w_out, b_out, out);
}

// round 17
// speedup vs baseline: 1.0374x; 1.0374x over previous
#include <cuda_runtime.h>
#include <cuda_bf16.h>
#include <math.h>

// Problem constants
#define Bn   8
#define Ntok 1024
#define Dd   768
#define Hh   8
#define Ss   3072
#define HDd  384
#define Mtok 8192   // Bn*Ntok
#define KH   1536   // gemm3 split-K half

// ---------------- scratch (device globals; no allocation allowed) ----------------
__device__ __align__(16) float g_xn[(size_t)Mtok * Dd];
__device__ __align__(16) float g_q [(size_t)Mtok * Ss];   // reused as gemm3 partials [2][Mtok][Dd]
__device__ __align__(16) float g_k [(size_t)Mtok * Ss];
__device__ __align__(16) float g_v [(size_t)Mtok * Ss];
__device__ __align__(16) float g_y [(size_t)Mtok * Ss];
__device__ __align__(16) float g_mem[(size_t)Hh * HDd * HDd];
__device__ float g_xpart[8 * Bn * Dd];
__device__ float g_kpart[4 * Bn * Ss];
__device__ float g_residue[Mtok];
__device__ float g_read[Bn * Hh];
__device__ float g_wbar[Hh];

// A-smem row stride (floats)
#define ASTR 132

// ---------------- packed f32x2 helpers (Blackwell double-rate FP32) ----------------
#define PACK2(dst, lo, hi) \
    asm("mov.b64 %0, {%1, %2};" : "=l"(dst) : "f"(lo), "f"(hi))
#define UNPACK2(lo, hi, src) \
    asm("mov.b64 {%0, %1}, %2;" : "=f"(lo), "=f"(hi) : "l"(src))
#define FMA2(acc, a, b) \
    asm("fma.rn.f32x2 %0, %1, %2, %0;" : "+l"(acc) : "l"(a), "l"(b))

// ---------------- 1. LayerNorm + residue gate (warp-per-token, no barriers) ----------------
__global__ void ln_kernel(const float* __restrict__ x, const float* __restrict__ ln_g,
                          const float* __restrict__ ln_b, const float* __restrict__ w_res,
                          const float* __restrict__ b_res) {
    int warp = threadIdx.x >> 5, lane = threadIdx.x & 31;
    int m = blockIdx.x * 8 + warp;
    const float* xr = x + (size_t)m * Dd;
    float v[24]; float s = 0.f, sq = 0.f;
    #pragma unroll
    for (int i = 0; i < 24; i++) {
        float t = xr[lane + 32 * i];
        v[i] = t; s += t; sq += t * t;
    }
    #pragma unroll
    for (int o = 16; o; o >>= 1) {
        s  += __shfl_xor_sync(0xffffffffu, s,  o);
        sq += __shfl_xor_sync(0xffffffffu, sq, o);
    }
    float mu   = s * (1.f / Dd);
    float var  = sq * (1.f / Dd) - mu * mu;
    float rstd = rsqrtf(var + 1e-5f);
    float dot = 0.f;
    #pragma unroll
    for (int i = 0; i < 24; i++) {
        int d = lane + 32 * i;
        float xn = (v[i] - mu) * rstd * ln_g[d] + ln_b[d];
        g_xn[(size_t)m * Dd + d] = xn;
        dot += xn * w_res[d];
    }
    #pragma unroll
    for (int o = 16; o; o >>= 1) dot += __shfl_xor_sync(0xffffffffu, dot, o);
    if (lane == 0) g_residue[m] = 1.f / (1.f + expf(-(dot + b_res[0])));
}

// ---------------- 2a. token-sum partials of xn ----------------
__global__ void xpart_kernel() {
    int b = blockIdx.x >> 3, c = blockIdx.x & 7;
    int d = blockIdx.y * 256 + threadIdx.x;
    const float* base = g_xn + ((size_t)(b * Ntok + c * 128)) * Dd + d;
    float s = 0.f;
    for (int n = 0; n < 128; n++) s += base[(size_t)n * Dd];
    g_xpart[((size_t)c * Bn + b) * Dd + d] = s;
}

// ---------------- 2b. read/write gates + write-mean ----------------
__global__ void gates_kernel(const float* __restrict__ w_rg, const float* __restrict__ b_rg,
                             const float* __restrict__ w_wg, const float* __restrict__ b_wg) {
    __shared__ float s_gate[2][64];
    int tid = threadIdx.x, warp = tid >> 5, lane = tid & 31;
    for (int job = warp; job < 128; job += 8) {
        int gate = job & 1, bh = job >> 1, b = bh >> 3, h = bh & 7;
        const float* W = gate ? w_wg : w_rg;
        float sacc = 0.f;
        for (int d = lane; d < Dd; d += 32) {
            float xm = 0.f;
            #pragma unroll
            for (int c = 0; c < 8; c++) xm += g_xpart[((size_t)c * Bn + b) * Dd + d];
            sacc += xm * W[(size_t)d * Hh + h];
        }
        #pragma unroll
        for (int o = 16; o; o >>= 1) sacc += __shfl_xor_sync(0xffffffffu, sacc, o);
        if (lane == 0) {
            float bias = gate ? b_wg[h] : b_rg[h];
            s_gate[gate][bh] = 1.f / (1.f + expf(-(sacc * (1.f / Ntok) + bias)));
        }
    }
    __syncthreads();
    if (tid < 64) g_read[tid] = s_gate[0][tid];
    if (tid < 8) {
        float s = 0.f;
        #pragma unroll
        for (int b = 0; b < 8; b++) s += s_gate[1][b * Hh + tid];
        g_wbar[tid] = s * (1.f / Bn);
    }
}

// ---------------- 3. GEMM1: qkv = xn @ w_in + b_in, fused activation split ----------------
__global__ void gemm1_kernel(const float* __restrict__ w_in, const float* __restrict__ b_in) {
    const int K = Dd, NN = 3 * Ss;
    __shared__ float As[2][8 * ASTR];
    __shared__ float Bs[2][8 * 128];
    int tid = threadIdx.x;
    int bRow = blockIdx.y * 128, bCol = blockIdx.x * 128;
    int aR0 = tid >> 1, aC0 = (tid & 1) * 4;
    int bR0 = tid >> 5, bC0 = (tid & 31) * 4;
    const float* Aptr = g_xn + (size_t)bRow * K;
    const float* Bptr = w_in + bCol;
    unsigned long long acc2[8][4] = {};
    int ra = (tid >> 4) * 4, cb = (tid & 15) * 4;

    float4 pa = *(const float4*)(Aptr + (size_t)aR0 * K + aC0);
    float4 pb = *(const float4*)(Bptr + (size_t)bR0 * NN + bC0);
    As[0][(aC0 + 0) * ASTR + aR0] = pa.x;  As[0][(aC0 + 1) * ASTR + aR0] = pa.y;
    As[0][(aC0 + 2) * ASTR + aR0] = pa.z;  As[0][(aC0 + 3) * ASTR + aR0] = pa.w;
    *(float4*)&Bs[0][bR0 * 128 + bC0] = pb;
    __syncthreads();

    const int KT = K / 8;
    for (int kt = 0; kt < KT; kt++) {
        int s = kt & 1;
        bool pre = (kt + 1 < KT);
        if (pre) {
            int kc = (kt + 1) * 8;
            pa = *(const float4*)(Aptr + (size_t)aR0 * K + kc + aC0);
            pb = *(const float4*)(Bptr + (size_t)(kc + bR0) * NN + bC0);
        }
        #pragma unroll
        for (int kk = 0; kk < 8; kk++) {
            float rM[8];
            *(float4*)&rM[0] = *(const float4*)&As[s][kk * ASTR + ra];
            *(float4*)&rM[4] = *(const float4*)&As[s][kk * ASTR + ra + 64];
            __align__(16) unsigned long long b2[4];
            *(float4*)&b2[0] = *(const float4*)&Bs[s][kk * 128 + cb];
            *(float4*)&b2[2] = *(const float4*)&Bs[s][kk * 128 + cb + 64];
            #pragma unroll
            for (int i = 0; i < 8; i++) {
                unsigned long long a2;
                PACK2(a2, rM[i], rM[i]);
                FMA2(acc2[i][0], a2, b2[0]);
                FMA2(acc2[i][1], a2, b2[1]);
                FMA2(acc2[i][2], a2, b2[2]);
                FMA2(acc2[i][3], a2, b2[3]);
            }
        }
        if (pre) {
            int d = s ^ 1;
            As[d][(aC0 + 0) * ASTR + aR0] = pa.x;  As[d][(aC0 + 1) * ASTR + aR0] = pa.y;
            As[d][(aC0 + 2) * ASTR + aR0] = pa.z;  As[d][(aC0 + 3) * ASTR + aR0] = pa.w;
            *(float4*)&Bs[d][bR0 * 128 + bC0] = pb;
            __syncthreads();
        }
    }

    float acc[8][8];
    #pragma unroll
    for (int i = 0; i < 8; i++) {
        UNPACK2(acc[i][0], acc[i][1], acc2[i][0]);
        UNPACK2(acc[i][2], acc[i][3], acc2[i][1]);
        UNPACK2(acc[i][4], acc[i][5], acc2[i][2]);
        UNPACK2(acc[i][6], acc[i][7], acc2[i][3]);
    }

    int region = bCol / Ss;                 // uniform per block: 0=q, 1=k, 2=v
    float* dst = (region == 0) ? g_q : (region == 1 ? g_k : g_v);
    int colBase = bCol - region * Ss;
    #pragma unroll
    for (int i = 0; i < 8; i++) {
        int row = bRow + ra + (i < 4 ? i : 64 + i - 4);
        #pragma unroll
        for (int half = 0; half < 2; half++) {
            int cB = cb + half * 64;
            float4 v;
            v.x = acc[i][half * 4 + 0] + b_in[bCol + cB + 0];
            v.y = acc[i][half * 4 + 1] + b_in[bCol + cB + 1];
            v.z = acc[i][half * 4 + 2] + b_in[bCol + cB + 2];
            v.w = acc[i][half * 4 + 3] + b_in[bCol + cB + 3];
            if (region < 2) {
                float t;
                t = fmaxf(v.x, 0.f) + 1e-6f; v.x = t * sqrtf(t);
                t = fmaxf(v.y, 0.f) + 1e-6f; v.y = t * sqrtf(t);
                t = fmaxf(v.z, 0.f) + 1e-6f; v.z = t * sqrtf(t);
                t = fmaxf(v.w, 0.f) + 1e-6f; v.w = t * sqrtf(t);
            }
            *(float4*)(dst + (size_t)row * Ss + colBase + cB) = v;
        }
    }
}

// ---------------- 4. token-sum partials of k-hat ----------------
__global__ void kpart_kernel() {
    int b = blockIdx.x;
    int s = blockIdx.y * 256 + threadIdx.x;
    int c = blockIdx.z;
    const float* base = g_k + ((size_t)(b * Ntok + c * 256)) * Ss + s;
    float s0 = 0.f, s1 = 0.f, s2 = 0.f, s3 = 0.f;
    for (int n = 0; n < 256; n += 4) {
        s0 += base[(size_t)(n + 0) * Ss];
        s1 += base[(size_t)(n + 1) * Ss];
        s2 += base[(size_t)(n + 2) * Ss];
        s3 += base[(size_t)(n + 3) * Ss];
    }
    g_kpart[((size_t)c * Bn + b) * Ss + s] = (s0 + s1) + (s2 + s3);
}

// ---------------- 5. per-head state (k^T v, normalized) + EMA memory update ----------------
__global__ void state_kernel(const float* __restrict__ memory) {
    int h = blockIdx.z, d0 = blockIdx.y * 64, e0 = blockIdx.x * 64;
    __shared__ float ks[32][64];
    __shared__ float vs[32][64];
    int tid = threadIdx.x;
    int tr = (tid >> 4) * 4, tc = (tid & 15) * 4;
    int n1 = tid >> 4, c1 = (tid & 15) * 4;
    float accT[4][4] = {};
    for (int b = 0; b < Bn; b++) {
        unsigned long long accB2[4][2] = {};
        const float* kbase = g_k + (size_t)b * Ntok * Ss + h * HDd + d0;
        const float* vbase = g_v + (size_t)b * Ntok * Ss + h * HDd + e0;
        for (int n0 = 0; n0 < Ntok; n0 += 32) {
            *(float4*)&ks[n1][c1]      = *(const float4*)(kbase + (size_t)(n0 + n1) * Ss + c1);
            *(float4*)&ks[n1 + 16][c1] = *(const float4*)(kbase + (size_t)(n0 + n1 + 16) * Ss + c1);
            *(float4*)&vs[n1][c1]      = *(const float4*)(vbase + (size_t)(n0 + n1) * Ss + c1);
            *(float4*)&vs[n1 + 16][c1] = *(const float4*)(vbase + (size_t)(n0 + n1 + 16) * Ss + c1);
            __syncthreads();
            #pragma unroll
            for (int n = 0; n < 32; n++) {
                float rk[4];
                *(float4*)&rk[0] = *(const float4*)&ks[n][tr];
                __align__(16) unsigned long long b2[2];
                *(float4*)&b2[0] = *(const float4*)&vs[n][tc];
                #pragma unroll
                for (int i = 0; i < 4; i++) {
                    unsigned long long a2;
                    PACK2(a2, rk[i], rk[i]);
                    FMA2(accB2[i][0], a2, b2[0]);
                    FMA2(accB2[i][1], a2, b2[1]);
                }
            }
            __syncthreads();
        }
        #pragma unroll
        for (int i = 0; i < 4; i++) {
            float accB[4];
            UNPACK2(accB[0], accB[1], accB2[i][0]);
            UNPACK2(accB[2], accB[3], accB2[i][1]);
            float kd = 0.f;
            #pragma unroll
            for (int c = 0; c < 4; c++)
                kd += g_kpart[((size_t)c * Bn + b) * Ss + h * HDd + d0 + tr + i];
            float rs = (1.f / Bn) / (kd + 1e-6f);
            #pragma unroll
            for (int j = 0; j < 4; j++) accT[i][j] += accB[j] * rs;
        }
    }
    float wb = g_wbar[h];
    #pragma unroll
    for (int i = 0; i < 4; i++)
        #pragma unroll
        for (int j = 0; j < 4; j++) {
            size_t idx = ((size_t)h * HDd + (d0 + tr + i)) * HDd + (e0 + tc + j);
            g_mem[idx] = 0.95f * memory[idx] + 0.05f * wb * accT[i][j];
        }
}

// ---------------- 6. GEMM2: y = read[b,h] * (q_h @ mem_new_h) ----------------
__global__ void gemm2_kernel() {
    const int K = HDd, NN = HDd;
    __shared__ float As[2][8 * ASTR];
    __shared__ float Bs[2][8 * 128];
    int tid = threadIdx.x;
    int h = blockIdx.z;
    int bRow = blockIdx.y * 128, bCol = blockIdx.x * 128;
    int aR0 = tid >> 1, aC0 = (tid & 1) * 4;
    int bR0 = tid >> 5, bC0 = (tid & 31) * 4;
    const float* Aptr = g_q + (size_t)bRow * Ss + h * HDd;
    const float* Bptr = g_mem + (size_t)h * HDd * HDd + bCol;
    unsigned long long acc2[8][4] = {};
    int ra = (tid >> 4) * 4, cb = (tid & 15) * 4;

    float4 pa = *(const float4*)(Aptr + (size_t)aR0 * Ss + aC0);
    float4 pb = *(const float4*)(Bptr + (size_t)bR0 * NN + bC0);
    As[0][(aC0 + 0) * ASTR + aR0] = pa.x;  As[0][(aC0 + 1) * ASTR + aR0] = pa.y;
    As[0][(aC0 + 2) * ASTR + aR0] = pa.z;  As[0][(aC0 + 3) * ASTR + aR0] = pa.w;
    *(float4*)&Bs[0][bR0 * 128 + bC0] = pb;
    __syncthreads();

    const int KT = K / 8;
    for (int kt = 0; kt < KT; kt++) {
        int s = kt & 1;
        bool pre = (kt + 1 < KT);
        if (pre) {
            int kc = (kt + 1) * 8;
            pa = *(const float4*)(Aptr + (size_t)aR0 * Ss + kc + aC0);
            pb = *(const float4*)(Bptr + (size_t)(kc + bR0) * NN + bC0);
        }
        #pragma unroll
        for (int kk = 0; kk < 8; kk++) {
            float rM[8];
            *(float4*)&rM[0] = *(const float4*)&As[s][kk * ASTR + ra];
            *(float4*)&rM[4] = *(const float4*)&As[s][kk * ASTR + ra + 64];
            __align__(16) unsigned long long b2[4];
            *(float4*)&b2[0] = *(const float4*)&Bs[s][kk * 128 + cb];
            *(float4*)&b2[2] = *(const float4*)&Bs[s][kk * 128 + cb + 64];
            #pragma unroll
            for (int i = 0; i < 8; i++) {
                unsigned long long a2;
                PACK2(a2, rM[i], rM[i]);
                FMA2(acc2[i][0], a2, b2[0]);
                FMA2(acc2[i][1], a2, b2[1]);
                FMA2(acc2[i][2], a2, b2[2]);
                FMA2(acc2[i][3], a2, b2[3]);
            }
        }
        if (pre) {
            int d = s ^ 1;
            As[d][(aC0 + 0) * ASTR + aR0] = pa.x;  As[d][(aC0 + 1) * ASTR + aR0] = pa.y;
            As[d][(aC0 + 2) * ASTR + aR0] = pa.z;  As[d][(aC0 + 3) * ASTR + aR0] = pa.w;
            *(float4*)&Bs[d][bR0 * 128 + bC0] = pb;
            __syncthreads();
        }
    }

    float acc[8][8];
    #pragma unroll
    for (int i = 0; i < 8; i++) {
        UNPACK2(acc[i][0], acc[i][1], acc2[i][0]);
        UNPACK2(acc[i][2], acc[i][3], acc2[i][1]);
        UNPACK2(acc[i][4], acc[i][5], acc2[i][2]);
        UNPACK2(acc[i][6], acc[i][7], acc2[i][3]);
    }

    float scale = g_read[(bRow >> 10) * Hh + h];   // 128-row tile lies within one batch
    #pragma unroll
    for (int i = 0; i < 8; i++) {
        int row = bRow + ra + (i < 4 ? i : 64 + i - 4);
        #pragma unroll
        for (int half = 0; half < 2; half++) {
            int cB = cb + half * 64;
            float4 v;
            v.x = acc[i][half * 4 + 0] * scale;
            v.y = acc[i][half * 4 + 1] * scale;
            v.z = acc[i][half * 4 + 2] * scale;
            v.w = acc[i][half * 4 + 3] * scale;
            *(float4*)(g_y + (size_t)row * Ss + h * HDd + bCol + cB) = v;
        }
    }
}

// ---------------- 7a. GEMM3 split-K phase: partial[half] = y[:, halfK] @ w_out[halfK, :] ----------------
// Partials stored raw into g_q (dead after gemm2): g_q[(half*Mtok + row)*Dd + col].
__global__ void gemm3a_kernel(const float* __restrict__ w_out) {
    const int NN = Dd;
    __shared__ float As[2][8 * ASTR];
    __shared__ float Bs[2][8 * 128];
    int tid = threadIdx.x;
    int halfK = blockIdx.z;
    int bRow = blockIdx.y * 128, bCol = blockIdx.x * 128;
    int aR0 = tid >> 1, aC0 = (tid & 1) * 4;
    int bR0 = tid >> 5, bC0 = (tid & 31) * 4;
    const float* Aptr = g_y + (size_t)bRow * Ss + halfK * KH;
    const float* Bptr = w_out + (size_t)(halfK * KH) * NN + bCol;
    unsigned long long acc2[8][4] = {};
    int ra = (tid >> 4) * 4, cb = (tid & 15) * 4;

    float4 pa = *(const float4*)(Aptr + (size_t)aR0 * Ss + aC0);
    float4 pb = *(const float4*)(Bptr + (size_t)bR0 * NN + bC0);
    As[0][(aC0 + 0) * ASTR + aR0] = pa.x;  As[0][(aC0 + 1) * ASTR + aR0] = pa.y;
    As[0][(aC0 + 2) * ASTR + aR0] = pa.z;  As[0][(aC0 + 3) * ASTR + aR0] = pa.w;
    *(float4*)&Bs[0][bR0 * 128 + bC0] = pb;
    __syncthreads();

    const int KT = KH / 8;
    for (int kt = 0; kt < KT; kt++) {
        int s = kt & 1;
        bool pre = (kt + 1 < KT);
        if (pre) {
            int kc = (kt + 1) * 8;
            pa = *(const float4*)(Aptr + (size_t)aR0 * Ss + kc + aC0);
            pb = *(const float4*)(Bptr + (size_t)(kc + bR0) * NN + bC0);
        }
        #pragma unroll
        for (int kk = 0; kk < 8; kk++) {
            float rM[8];
            *(float4*)&rM[0] = *(const float4*)&As[s][kk * ASTR + ra];
            *(float4*)&rM[4] = *(const float4*)&As[s][kk * ASTR + ra + 64];
            __align__(16) unsigned long long b2[4];
            *(float4*)&b2[0] = *(const float4*)&Bs[s][kk * 128 + cb];
            *(float4*)&b2[2] = *(const float4*)&Bs[s][kk * 128 + cb + 64];
            #pragma unroll
            for (int i = 0; i < 8; i++) {
                unsigned long long a2;
                PACK2(a2, rM[i], rM[i]);
                FMA2(acc2[i][0], a2, b2[0]);
                FMA2(acc2[i][1], a2, b2[1]);
                FMA2(acc2[i][2], a2, b2[2]);
                FMA2(acc2[i][3], a2, b2[3]);
            }
        }
        if (pre) {
            int d = s ^ 1;
            As[d][(aC0 + 0) * ASTR + aR0] = pa.x;  As[d][(aC0 + 1) * ASTR + aR0] = pa.y;
            As[d][(aC0 + 2) * ASTR + aR0] = pa.z;  As[d][(aC0 + 3) * ASTR + aR0] = pa.w;
            *(float4*)&Bs[d][bR0 * 128 + bC0] = pb;
            __syncthreads();
        }
    }

    float* pdst = g_q + (size_t)halfK * Mtok * Dd;
    #pragma unroll
    for (int i = 0; i < 8; i++) {
        int row = bRow + ra + (i < 4 ? i : 64 + i - 4);
        #pragma unroll
        for (int half = 0; half < 2; half++) {
            int cB = bCol + cb + half * 64;
            float4 v;
            UNPACK2(v.x, v.y, acc2[i][half * 2 + 0]);
            UNPACK2(v.z, v.w, acc2[i][half * 2 + 1]);
            *(float4*)(pdst + (size_t)row * Dd + cB) = v;
        }
    }
}

// ---------------- 7b. GEMM3 combine: out = residue*((p0+p1)+b_out) + (1-residue)*x ----------------
__global__ void gemm3b_kernel(const float* __restrict__ x, const float* __restrict__ b_out,
                              float* __restrict__ out) {
    int idx = blockIdx.x * 256 + threadIdx.x;      // float4 index
    int m = idx / (Dd / 4);
    int c4 = (idx % (Dd / 4)) * 4;
    float r = g_residue[m];
    float4 p0 = *(const float4*)(g_q + (size_t)m * Dd + c4);
    float4 p1 = *(const float4*)(g_q + ((size_t)Mtok + m) * Dd + c4);
    float4 bo = *(const float4*)(b_out + c4);
    float4 xv = *(const float4*)(x + (size_t)m * Dd + c4);
    float4 v;
    v.x = r * ((p0.x + p1.x) + bo.x) + (1.f - r) * xv.x;
    v.y = r * ((p0.y + p1.y) + bo.y) + (1.f - r) * xv.y;
    v.z = r * ((p0.z + p1.z) + bo.z) + (1.f - r) * xv.z;
    v.w = r * ((p0.w + p1.w) + bo.w) + (1.f - r) * xv.w;
    *(float4*)(out + (size_t)m * Dd + c4) = v;
}

// ---------------- launch ----------------
extern "C" void kernel_launch(void* const* d_in, const int* in_sizes, int n_in,
                              void* d_out, int out_size) {
    (void)in_sizes; (void)n_in; (void)out_size;
    const float* x      = (const float*)d_in[0];
    const float* memory = (const float*)d_in[1];
    const float* ln_g   = (const float*)d_in[2];
    const float* ln_b   = (const float*)d_in[3];
    const float* w_in   = (const float*)d_in[4];
    const float* b_in   = (const float*)d_in[5];
    const float* w_out  = (const float*)d_in[6];
    const float* b_out  = (const float*)d_in[7];
    const float* w_rg   = (const float*)d_in[8];
    const float* b_rg   = (const float*)d_in[9];
    const float* w_wg   = (const float*)d_in[10];
    const float* b_wg   = (const float*)d_in[11];
    const float* w_res  = (const float*)d_in[12];
    const float* b_res  = (const float*)d_in[13];
    float* out = (float*)d_out;

    ln_kernel<<<Mtok / 8, 256>>>(x, ln_g, ln_b, w_res, b_res);
    xpart_kernel<<<dim3(64, 3), 256>>>();
    gates_kernel<<<1, 256>>>(w_rg, b_rg, w_wg, b_wg);
    gemm1_kernel<<<dim3(72, 64), 256>>>(w_in, b_in);
    kpart_kernel<<<dim3(8, 12, 4), 256>>>();
    state_kernel<<<dim3(6, 6, 8), 256>>>(memory);
    gemm2_kernel<<<dim3(3, 64, 8), 256>>>();
    gemm3a_kernel<<<dim3(6, 64, 2), 256>>>(w_out);
    gemm3b_kernel<<<Mtok * Dd / 1024, 256>>>(x, b_out, out);
}